// round 4
// baseline (speedup 1.0000x reference)
#include <cuda_runtime.h>

// ---------------------------------------------------------------------------
// SSIM fused single-kernel: 5 separable 11-tap Gaussian blurs + SSIM + mean.
// Channels paired into f32x2 (packed FFMA2 via PTX fma.rn.f32x2):
//   plane AB = (img1, img2), plane SQ = (img1^2, img2^2), plane P = img1*img2.
// Tile 32x64 outputs/block, 256 threads, in-place horizontal pass,
// swizzled columns (c+r)&31 for conflict-free STS/LDS, last-block finalize.
// ---------------------------------------------------------------------------

typedef unsigned long long ull;

#define IMG      512
#define TW       32
#define TH       64
#define HALO     5
#define ROWS     74               // TH + 2*HALO
#define SROW2    46               // float2 row stride (f32x2 planes)
#define SROWP    44               // float  row stride (product plane)
#define NTHREADS 256
#define NBLOCKS  (16 * 8 * 64)    // 8192

#define SSIM_C1 0.0001f
#define SSIM_C2 0.0009f

// 1-D Gaussian, sigma=1.5, 11 taps, normalized
#define GW0 1.0283735e-03f
#define GW1 7.5987582e-03f
#define GW2 3.6000773e-02f
#define GW3 1.0936068e-01f
#define GW4 2.1300554e-01f
#define GW5 2.6601174e-01f

// scalar conv: literal taps -> FFMA-with-immediate (rt_SMSP=1)
#define CONV11(X, c)                                                      \
    fmaf(GW0, (X)[(c)+0], fmaf(GW1, (X)[(c)+1], fmaf(GW2, (X)[(c)+2],     \
    fmaf(GW3, (X)[(c)+3], fmaf(GW4, (X)[(c)+4], fmaf(GW5, (X)[(c)+5],     \
    fmaf(GW4, (X)[(c)+6], fmaf(GW3, (X)[(c)+7], fmaf(GW2, (X)[(c)+8],     \
    fmaf(GW1, (X)[(c)+9], GW0 * (X)[(c)+10]))))))))))

__device__ __forceinline__ ull pk2(float lo, float hi) {
    ull d; asm("mov.b64 %0, {%1, %2};" : "=l"(d) : "f"(lo), "f"(hi)); return d;
}
__device__ __forceinline__ void unpk2(ull v, float& lo, float& hi) {
    asm("mov.b64 {%0, %1}, %2;" : "=f"(lo), "=f"(hi) : "l"(v));
}
__device__ __forceinline__ ull mul2(ull a, ull b) {
    ull d; asm("mul.rn.f32x2 %0, %1, %2;" : "=l"(d) : "l"(a), "l"(b)); return d;
}
__device__ __forceinline__ ull fma2(ull a, ull b, ull c) {
    ull d; asm("fma.rn.f32x2 %0, %1, %2, %3;" : "=l"(d) : "l"(a), "l"(b), "l"(c)); return d;
}
// packed 11-tap conv (symmetric taps W[0..5])
__device__ __forceinline__ ull conv2(const ull* x, int c, const ull* W) {
    ull a = mul2(W[0], x[c]);
    a = fma2(W[1], x[c + 1], a);
    a = fma2(W[2], x[c + 2], a);
    a = fma2(W[3], x[c + 3], a);
    a = fma2(W[4], x[c + 4], a);
    a = fma2(W[5], x[c + 5], a);
    a = fma2(W[4], x[c + 6], a);
    a = fma2(W[3], x[c + 7], a);
    a = fma2(W[2], x[c + 8], a);
    a = fma2(W[1], x[c + 9], a);
    a = fma2(W[0], x[c + 10], a);
    return a;
}

static __device__ double   g_acc = 0.0;
static __device__ unsigned g_cnt = 0u;

// smem: AB[74][46] f32x2 + SQ[74][46] f32x2 + P[74][44] f32   = 67,488 B
#define AB_OFF 0
#define SQ_OFF (ROWS * SROW2)                 // in float2 units
#define P_OFF  (2 * ROWS * SROW2 * 2)         // in float units
#define SMEM_BYTES (2 * ROWS * SROW2 * 8 + ROWS * SROWP * 4)

__global__ __launch_bounds__(NTHREADS, 2)
void ssim_kernel(const float* __restrict__ img1, const float* __restrict__ img2,
                 float* __restrict__ out) {
    extern __shared__ float smem[];
    float2* sAB = reinterpret_cast<float2*>(smem) + AB_OFF;
    float2* sSQ = reinterpret_cast<float2*>(smem) + SQ_OFF;
    float*  sP  = smem + P_OFF;
    __shared__ float red[8];

    const int t    = threadIdx.x;
    const int lane = t & 31;
    const int wid  = t >> 5;
    const int gx0  = blockIdx.x * TW - HALO;
    const int gy0  = blockIdx.y * TH - HALO;
    const float* base1 = img1 + (size_t)blockIdx.z * (IMG * IMG);
    const float* base2 = img2 + (size_t)blockIdx.z * (IMG * IMG);

    // ---- Phase 1: load (zero-padded) + products. Warp per row, coalesced. ----
    for (int r = wid; r < ROWS; r += 8) {
        const int gy = gy0 + r;
        const bool yok = (unsigned)gy < (unsigned)IMG;
        const float* r1 = base1 + gy * IMG;
        const float* r2 = base2 + gy * IMG;
#pragma unroll
        for (int seg = 0; seg < 2; seg++) {
            const int c = lane + seg * 32;
            if (seg == 1 && lane >= 10) break;
            const int gx = gx0 + c;
            const bool ok = yok && (unsigned)gx < (unsigned)IMG;
            const float a = ok ? r1[gx] : 0.0f;
            const float b = ok ? r2[gx] : 0.0f;
            sAB[r * SROW2 + c] = make_float2(a, b);
            sSQ[r * SROW2 + c] = make_float2(a * a, b * b);
            sP [r * SROWP + c] = a * b;
        }
    }
    __syncthreads();

    // ---- Phase 2: horizontal blur, in-place, one pass (222 strips) ----
    if (t < 2 * ROWS) {
        // packed strip: t<74 -> AB row t ; else SQ row t-74
        const int arr = (t >= ROWS);
        const int r   = t - arr * ROWS;
        float2* rowf2 = (arr ? sSQ : sAB) + r * SROW2;
        ull W[6] = { pk2(GW0,GW0), pk2(GW1,GW1), pk2(GW2,GW2),
                     pk2(GW3,GW3), pk2(GW4,GW4), pk2(GW5,GW5) };
        ull x[44];
        const ulonglong2* v = reinterpret_cast<const ulonglong2*>(rowf2);
#pragma unroll
        for (int i = 0; i < 21; i++) {            // cols 0..41 (42,43 unused)
            const ulonglong2 q = v[i];
            x[2 * i]     = q.x;
            x[2 * i + 1] = q.y;
        }
#pragma unroll
        for (int c = 0; c < TW; c++) {
            const ull acc = conv2(x, c, W);
            *reinterpret_cast<ull*>(rowf2 + ((c + r) & 31)) = acc;
        }
    } else if (t < 2 * ROWS + ROWS) {
        const int r = t - 2 * ROWS;
        float* row = sP + r * SROWP;
        float x[44];
#pragma unroll
        for (int i = 0; i < 11; i++) {
            const float4 q = *reinterpret_cast<const float4*>(row + 4 * i);
            x[4 * i + 0] = q.x; x[4 * i + 1] = q.y;
            x[4 * i + 2] = q.z; x[4 * i + 3] = q.w;
        }
#pragma unroll
        for (int c = 0; c < TW; c++) {
            row[(c + r) & 31] = CONV11(x, c);
        }
    }
    __syncthreads();

    // ---- Phase 3: vertical blur (8 rows/thread, packed) + SSIM + reduce ----
    {
        ull W[6] = { pk2(GW0,GW0), pk2(GW1,GW1), pk2(GW2,GW2),
                     pk2(GW3,GW3), pk2(GW4,GW4), pk2(GW5,GW5) };
        const int col = lane;
        const int r0  = wid * 8;

        ull y[18];
#pragma unroll
        for (int j = 0; j < 18; j++) {
            const int rr = r0 + j;
            y[j] = *reinterpret_cast<const ull*>(sAB + rr * SROW2 + ((col + rr) & 31));
        }
        ull mu[8];
#pragma unroll
        for (int i = 0; i < 8; i++) mu[i] = conv2(y, i, W);

#pragma unroll
        for (int j = 0; j < 18; j++) {
            const int rr = r0 + j;
            y[j] = *reinterpret_cast<const ull*>(sSQ + rr * SROW2 + ((col + rr) & 31));
        }
        ull sq[8];
#pragma unroll
        for (int i = 0; i < 8; i++) sq[i] = conv2(y, i, W);

        float yp[18];
#pragma unroll
        for (int j = 0; j < 18; j++) {
            const int rr = r0 + j;
            yp[j] = sP[rr * SROWP + ((col + rr) & 31)];
        }

        float lsum = 0.0f;
#pragma unroll
        for (int i = 0; i < 8; i++) {
            float m1, m2, e11, e22;
            unpk2(mu[i], m1, m2);
            unpk2(sq[i], e11, e22);
            const float e12 = CONV11(yp, i);
            const float m1s = m1 * m1;
            const float m2s = m2 * m2;
            const float m12 = m1 * m2;
            const float s1  = e11 - m1s;
            const float s2  = e22 - m2s;
            const float s12 = e12 - m12;
            const float num = (2.0f * m12 + SSIM_C1) * (2.0f * s12 + SSIM_C2);
            const float den = (m1s + m2s + SSIM_C1) * (s1 + s2 + SSIM_C2);
            lsum += __fdividef(num, den);
        }

        // warp reduce -> block reduce -> global atomic
#pragma unroll
        for (int off = 16; off > 0; off >>= 1)
            lsum += __shfl_xor_sync(0xffffffffu, lsum, off);
        if (lane == 0) red[wid] = lsum;
        __syncthreads();
        if (t == 0) {
            float s = 0.0f;
#pragma unroll
            for (int i = 0; i < 8; i++) s += red[i];
            atomicAdd(&g_acc, (double)s);
            __threadfence();
            const unsigned old = atomicAdd(&g_cnt, 1u);
            if (old == NBLOCKS - 1) {
                // last block: read+reset accumulator atomically, finalize
                const ull raw = atomicExch(reinterpret_cast<ull*>(&g_acc), 0ull);
                out[0] = (float)(__longlong_as_double(raw) * (1.0 / 16777216.0));
                g_cnt = 0u;
            }
        }
    }
}

extern "C" void kernel_launch(void* const* d_in, const int* in_sizes, int n_in,
                              void* d_out, int out_size) {
    const float* img1 = (const float*)d_in[0];
    const float* img2 = (const float*)d_in[1];
    float* out = (float*)d_out;

    cudaFuncSetAttribute(ssim_kernel,
                         cudaFuncAttributeMaxDynamicSharedMemorySize, SMEM_BYTES);

    dim3 grid(IMG / TW, IMG / TH, 64);   // 16 x 8 x 64 = 8192 blocks
    ssim_kernel<<<grid, NTHREADS, SMEM_BYTES>>>(img1, img2, out);
}

// round 5
// speedup vs baseline: 1.2852x; 1.2852x over previous
#include <cuda_runtime.h>

// ---------------------------------------------------------------------------
// SSIM fused single-kernel: 5 separable 11-tap Gaussian blurs + SSIM + mean.
// Scalar fp32, 5 smem planes. Tile 32x64 outputs/block, 512 threads,
// in-place horizontal pass (half-row strips), swizzled columns (c+r)&31
// (conflict-free STS/LDS), last-block finalize. launch_bounds(512,2) -> 50% occ.
// ---------------------------------------------------------------------------

typedef unsigned long long ull;

#define IMG      512
#define TW       32
#define TH       64
#define HALO     5
#define ROWS     74               // TH + 2*HALO
#define SROW     44               // row stride (floats), cols 0..41 valid
#define PLANE    (ROWS * SROW)    // 3256
#define NCH      5
#define NTHREADS 512
#define NBLOCKS  (16 * 8 * 64)    // 8192

#define SSIM_C1 0.0001f
#define SSIM_C2 0.0009f

// 1-D Gaussian, sigma=1.5, 11 taps, normalized (literals -> FFMA-imm)
#define GW0 1.0283735e-03f
#define GW1 7.5987582e-03f
#define GW2 3.6000773e-02f
#define GW3 1.0936068e-01f
#define GW4 2.1300554e-01f
#define GW5 2.6601174e-01f

#define CONV11(X, c)                                                      \
    fmaf(GW0, (X)[(c)+0], fmaf(GW1, (X)[(c)+1], fmaf(GW2, (X)[(c)+2],     \
    fmaf(GW3, (X)[(c)+3], fmaf(GW4, (X)[(c)+4], fmaf(GW5, (X)[(c)+5],     \
    fmaf(GW4, (X)[(c)+6], fmaf(GW3, (X)[(c)+7], fmaf(GW2, (X)[(c)+8],     \
    fmaf(GW1, (X)[(c)+9], GW0 * (X)[(c)+10]))))))))))

static __device__ double   g_acc = 0.0;
static __device__ unsigned g_cnt = 0u;

#define SMEM_BYTES (NCH * PLANE * (int)sizeof(float))   // 65,120 B

__global__ __launch_bounds__(NTHREADS, 2)
void ssim_kernel(const float* __restrict__ img1, const float* __restrict__ img2,
                 float* __restrict__ out) {
    extern __shared__ float sC[];   // [NCH][ROWS][SROW]
    __shared__ float red[16];

    const int t    = threadIdx.x;
    const int lane = t & 31;
    const int wid  = t >> 5;        // 0..15
    const int gx0  = blockIdx.x * TW - HALO;
    const int gy0  = blockIdx.y * TH - HALO;
    const float* base1 = img1 + (size_t)blockIdx.z * (IMG * IMG);
    const float* base2 = img2 + (size_t)blockIdx.z * (IMG * IMG);

    // ---- Phase 1: global load (zero-padded) + products. Warp per row. ----
    for (int r = wid; r < ROWS; r += 16) {
        const int gy = gy0 + r;
        const bool yok = (unsigned)gy < (unsigned)IMG;
        const float* r1 = base1 + gy * IMG;
        const float* r2 = base2 + gy * IMG;
        const int o = r * SROW;
#pragma unroll
        for (int seg = 0; seg < 2; seg++) {
            const int c = lane + seg * 32;
            if (seg == 1 && lane >= 10) break;
            const int gx = gx0 + c;
            const bool ok = yok && (unsigned)gx < (unsigned)IMG;
            const float a = ok ? r1[gx] : 0.0f;
            const float b = ok ? r2[gx] : 0.0f;
            sC[0 * PLANE + o + c] = a;
            sC[1 * PLANE + o + c] = b;
            sC[2 * PLANE + o + c] = a * a;
            sC[3 * PLANE + o + c] = b * b;
            sC[4 * PLANE + o + c] = a * b;
        }
    }
    __syncthreads();

    // ---- Phase 2: horizontal blur, in-place, half-row strips ----
    // 5 planes x 74 rows x 2 halves = 740 tasks; 16 outputs per task.
    // Register window: 28 floats (7x float4), outputs overwrite cols of the
    // same row AFTER all loads (thread-private row half; in-place safe because
    // the thread loaded everything it needs first).
    for (int u = t; u < NCH * ROWS * 2; u += NTHREADS) {
        const int p    = u / (ROWS * 2);
        const int rem  = u - p * (ROWS * 2);
        const int r    = rem >> 1;
        const int half = rem & 1;
        const int cbase = half * 16;
        float* row = &sC[p * PLANE + r * SROW];

        float x[28];
#pragma unroll
        for (int i = 0; i < 7; i++) {
            const float4 v = *reinterpret_cast<const float4*>(row + cbase + 4 * i);
            x[4 * i + 0] = v.x;
            x[4 * i + 1] = v.y;
            x[4 * i + 2] = v.z;
            x[4 * i + 3] = v.w;
        }
#pragma unroll
        for (int j = 0; j < 16; j++) {
            const int c = cbase + j;                 // output col 0..31
            row[(c + r) & 31] = CONV11(x, j);        // swizzled, conflict-free
        }
    }
    __syncthreads();

    // ---- Phase 3: vertical blur (4 rows/thread) + SSIM + reduction ----
    {
        const int col = lane;
        const int r0  = wid * 4;       // 16 warps x 4 rows = 64 output rows

        float res[NCH][4];
#pragma unroll
        for (int ch = 0; ch < NCH; ch++) {
            float y[14];
#pragma unroll
            for (int j = 0; j < 14; j++) {
                const int rr = r0 + j;
                y[j] = sC[ch * PLANE + rr * SROW + ((col + rr) & 31)];
            }
#pragma unroll
            for (int i = 0; i < 4; i++) res[ch][i] = CONV11(y, i);
        }

        float lsum = 0.0f;
#pragma unroll
        for (int i = 0; i < 4; i++) {
            const float m1  = res[0][i];
            const float m2  = res[1][i];
            const float m1s = m1 * m1;
            const float m2s = m2 * m2;
            const float m12 = m1 * m2;
            const float s1  = res[2][i] - m1s;
            const float s2  = res[3][i] - m2s;
            const float s12 = res[4][i] - m12;
            const float num = (2.0f * m12 + SSIM_C1) * (2.0f * s12 + SSIM_C2);
            const float den = (m1s + m2s + SSIM_C1) * (s1 + s2 + SSIM_C2);
            lsum += __fdividef(num, den);
        }

        // warp reduce -> block reduce -> one global atomic per block
#pragma unroll
        for (int off = 16; off > 0; off >>= 1)
            lsum += __shfl_xor_sync(0xffffffffu, lsum, off);
        if (lane == 0) red[wid] = lsum;
        __syncthreads();
        if (t == 0) {
            float s = 0.0f;
#pragma unroll
            for (int i = 0; i < 16; i++) s += red[i];
            atomicAdd(&g_acc, (double)s);
            __threadfence();
            const unsigned old = atomicAdd(&g_cnt, 1u);
            if (old == NBLOCKS - 1) {
                const ull raw = atomicExch(reinterpret_cast<ull*>(&g_acc), 0ull);
                out[0] = (float)(__longlong_as_double(raw) * (1.0 / 16777216.0));
                g_cnt = 0u;
            }
        }
    }
}

extern "C" void kernel_launch(void* const* d_in, const int* in_sizes, int n_in,
                              void* d_out, int out_size) {
    const float* img1 = (const float*)d_in[0];
    const float* img2 = (const float*)d_in[1];
    float* out = (float*)d_out;

    cudaFuncSetAttribute(ssim_kernel,
                         cudaFuncAttributeMaxDynamicSharedMemorySize, SMEM_BYTES);

    dim3 grid(IMG / TW, IMG / TH, 64);   // 16 x 8 x 64 = 8192 blocks
    ssim_kernel<<<grid, NTHREADS, SMEM_BYTES>>>(img1, img2, out);
}

// round 6
// speedup vs baseline: 1.3434x; 1.0452x over previous
#include <cuda_runtime.h>

// ---------------------------------------------------------------------------
// SSIM fused single-kernel: 5 separable 11-tap Gaussian blurs + SSIM + mean.
// Tile 32x64 outputs/block, 512 threads.
//   P1: global load (zero-pad) + products -> 5 smem planes [row][col]
//   P2: horizontal 11-tap conv -> TRANSPOSED H buffer [ch][col][row]
//   P3: vertical 11-tap conv via float4 LDS down columns + SSIM + reduce
// Transposed H makes P3 loads vectorized & conflict-free with zero swizzle ALU.
// ---------------------------------------------------------------------------

typedef unsigned long long ull;

#define IMG      512
#define TW       32
#define TH       64
#define HALO     5
#define ROWS     74               // TH + 2*HALO
#define SROW     44               // P1 row stride (floats), cols 0..41 valid
#define PLANE    (ROWS * SROW)    // 3256
#define NCH      5
#define NTHREADS 512
#define NBLOCKS  (16 * 8 * 64)    // 8192

#define HCOL     76               // H column stride (>=74, mult of 4, /4 odd)
#define HP       (32 * HCOL)      // H plane stride = 2432 floats
#define HOFF     (NCH * PLANE)    // H base offset = 16280 floats

#define SMEM_BYTES ((HOFF + NCH * HP) * (int)sizeof(float))   // 113,760 B

#define SSIM_C1 0.0001f
#define SSIM_C2 0.0009f

// 1-D Gaussian, sigma=1.5, 11 taps, normalized (literals -> FFMA-imm)
#define GW0 1.0283735e-03f
#define GW1 7.5987582e-03f
#define GW2 3.6000773e-02f
#define GW3 1.0936068e-01f
#define GW4 2.1300554e-01f
#define GW5 2.6601174e-01f

#define CONV11(X, c)                                                      \
    fmaf(GW0, (X)[(c)+0], fmaf(GW1, (X)[(c)+1], fmaf(GW2, (X)[(c)+2],     \
    fmaf(GW3, (X)[(c)+3], fmaf(GW4, (X)[(c)+4], fmaf(GW5, (X)[(c)+5],     \
    fmaf(GW4, (X)[(c)+6], fmaf(GW3, (X)[(c)+7], fmaf(GW2, (X)[(c)+8],     \
    fmaf(GW1, (X)[(c)+9], GW0 * (X)[(c)+10]))))))))))

static __device__ double   g_acc = 0.0;
static __device__ unsigned g_cnt = 0u;

__global__ __launch_bounds__(NTHREADS, 2)
void ssim_kernel(const float* __restrict__ img1, const float* __restrict__ img2,
                 float* __restrict__ out) {
    extern __shared__ float sC[];   // [5][74][44] then H: [5][32][76]
    __shared__ float red[16];

    const int t    = threadIdx.x;
    const int lane = t & 31;
    const int wid  = t >> 5;        // 0..15
    const int gx0  = blockIdx.x * TW - HALO;
    const int gy0  = blockIdx.y * TH - HALO;
    const float* base1 = img1 + (size_t)blockIdx.z * (IMG * IMG);
    const float* base2 = img2 + (size_t)blockIdx.z * (IMG * IMG);

    // ---- Phase 1: global load (zero-padded) + products. Warp per row. ----
    for (int r = wid; r < ROWS; r += 16) {
        const int gy = gy0 + r;
        const bool yok = (unsigned)gy < (unsigned)IMG;
        const float* r1 = base1 + gy * IMG;
        const float* r2 = base2 + gy * IMG;
        const int o = r * SROW;
#pragma unroll
        for (int seg = 0; seg < 2; seg++) {
            const int c = lane + seg * 32;
            if (seg == 1 && lane >= 10) break;
            const int gx = gx0 + c;
            const bool ok = yok && (unsigned)gx < (unsigned)IMG;
            const float a = ok ? r1[gx] : 0.0f;
            const float b = ok ? r2[gx] : 0.0f;
            sC[0 * PLANE + o + c] = a;
            sC[1 * PLANE + o + c] = b;
            sC[2 * PLANE + o + c] = a * a;
            sC[3 * PLANE + o + c] = b * b;
            sC[4 * PLANE + o + c] = a * b;
        }
    }
    __syncthreads();

    // ---- Phase 2: horizontal blur -> transposed H[ch][col][row] ----
    // 5 planes x 74 rows x 2 halves = 740 tasks, 16 outputs each.
    // Plane-major mapping keeps adjacent lanes on adjacent rows -> STS banks
    // (12c + r) conflict-free, no swizzle.
    for (int u = t; u < NCH * ROWS * 2; u += NTHREADS) {
        const int p    = u / (2 * ROWS);
        const int rem  = u - p * (2 * ROWS);
        const int half = rem / ROWS;        // 0 or 1
        const int r    = rem - half * ROWS; // 0..73
        const int cbase = half * 16;
        const float* row = &sC[p * PLANE + r * SROW + cbase];

        float x[28];
#pragma unroll
        for (int i = 0; i < 7; i++) {
            const float4 v = *reinterpret_cast<const float4*>(row + 4 * i);
            x[4 * i + 0] = v.x;
            x[4 * i + 1] = v.y;
            x[4 * i + 2] = v.z;
            x[4 * i + 3] = v.w;
        }
        float* hbase = &sC[HOFF + p * HP + cbase * HCOL + r];
#pragma unroll
        for (int j = 0; j < 16; j++) {
            hbase[j * HCOL] = CONV11(x, j);   // immediate offsets, no ALU
        }
    }
    __syncthreads();

    // ---- Phase 3: vertical blur via float4 column reads + SSIM + reduce ----
    {
        const int col = lane;
        const int r0  = wid * 4;       // 16 warps x 4 rows = 64 output rows

        float res[NCH][4];
#pragma unroll
        for (int ch = 0; ch < NCH; ch++) {
            const float* p = &sC[HOFF + ch * HP + col * HCOL + r0];
            float y[16];                // y[14],y[15] loaded but never used
#pragma unroll
            for (int i = 0; i < 4; i++) {
                const float4 v = *reinterpret_cast<const float4*>(p + 4 * i);
                y[4 * i + 0] = v.x;
                y[4 * i + 1] = v.y;
                y[4 * i + 2] = v.z;
                y[4 * i + 3] = v.w;
            }
#pragma unroll
            for (int i = 0; i < 4; i++) res[ch][i] = CONV11(y, i);
        }

        float lsum = 0.0f;
#pragma unroll
        for (int i = 0; i < 4; i++) {
            const float m1  = res[0][i];
            const float m2  = res[1][i];
            const float m1s = m1 * m1;
            const float m2s = m2 * m2;
            const float m12 = m1 * m2;
            const float s1  = res[2][i] - m1s;
            const float s2  = res[3][i] - m2s;
            const float s12 = res[4][i] - m12;
            const float num = (2.0f * m12 + SSIM_C1) * (2.0f * s12 + SSIM_C2);
            const float den = (m1s + m2s + SSIM_C1) * (s1 + s2 + SSIM_C2);
            lsum += __fdividef(num, den);
        }

        // warp reduce -> block reduce -> one global atomic per block
#pragma unroll
        for (int off = 16; off > 0; off >>= 1)
            lsum += __shfl_xor_sync(0xffffffffu, lsum, off);
        if (lane == 0) red[wid] = lsum;
        __syncthreads();
        if (t == 0) {
            float s = 0.0f;
#pragma unroll
            for (int i = 0; i < 16; i++) s += red[i];
            atomicAdd(&g_acc, (double)s);
            __threadfence();
            const unsigned old = atomicAdd(&g_cnt, 1u);
            if (old == NBLOCKS - 1) {
                const ull raw = atomicExch(reinterpret_cast<ull*>(&g_acc), 0ull);
                out[0] = (float)(__longlong_as_double(raw) * (1.0 / 16777216.0));
                g_cnt = 0u;
            }
        }
    }
}

extern "C" void kernel_launch(void* const* d_in, const int* in_sizes, int n_in,
                              void* d_out, int out_size) {
    const float* img1 = (const float*)d_in[0];
    const float* img2 = (const float*)d_in[1];
    float* out = (float*)d_out;

    cudaFuncSetAttribute(ssim_kernel,
                         cudaFuncAttributeMaxDynamicSharedMemorySize, SMEM_BYTES);

    dim3 grid(IMG / TW, IMG / TH, 64);   // 16 x 8 x 64 = 8192 blocks
    ssim_kernel<<<grid, NTHREADS, SMEM_BYTES>>>(img1, img2, out);
}

// round 8
// speedup vs baseline: 1.4786x; 1.1007x over previous
#include <cuda_runtime.h>

// ---------------------------------------------------------------------------
// SSIM fused single-kernel. Tile 32x64 outputs/block, 384 threads, 3 CTAs/SM.
//   P1: stage a,b (zero-padded) coalesced into smem      [2 planes, 26 KB]
//   P2: horizontal 11-tap conv of ALL 5 channels, products formed in-register
//       from a,b windows -> transposed H[ch][col][row]   [48.6 KB]
//   P3: vertical 11-tap conv via ALIGNED float4 column reads + SSIM + reduce
//       (loads from rb = r0 & ~3; warp-uniform dual path for residue 0/2)
// ---------------------------------------------------------------------------

typedef unsigned long long ull;

#define IMG      512
#define TW       32
#define TH       64
#define HALO     5
#define ROWS     74               // TH + 2*HALO
#define SROW     44               // a,b plane row stride (floats)
#define PLANE    (ROWS * SROW)    // 3256
#define NTHREADS 384
#define NWARPS   12
#define NBLOCKS  (16 * 8 * 64)    // 8192

#define HCOL     76               // H column stride (mult of 4)
#define HP       (32 * HCOL)      // 2432 floats per H plane
#define HOFF     (2 * PLANE)      // H starts after a,b planes (6512 floats)

// +16 floats pad: warp 11 loads y[20] from rb=60 -> reads 4 floats past the
// last H column; pad keeps it inside the allocation (values unused).
#define SMEM_BYTES ((HOFF + 5 * HP + 16) * (int)sizeof(float))   // 74,752 B

#define SSIM_C1 0.0001f
#define SSIM_C2 0.0009f

// 1-D Gaussian, sigma=1.5, 11 taps, normalized (literals -> FFMA-imm)
static __device__ __forceinline__ float gwk(int k) {
    const float g[11] = { 1.0283735e-03f, 7.5987582e-03f, 3.6000773e-02f,
                          1.0936068e-01f, 2.1300554e-01f, 2.6601174e-01f,
                          2.1300554e-01f, 1.0936068e-01f, 3.6000773e-02f,
                          7.5987582e-03f, 1.0283735e-03f };
    return g[k];   // k compile-time under full unroll -> immediate
}

#define CONV11(X, c)                                                          \
    fmaf(gwk(0), (X)[(c)+0], fmaf(gwk(1), (X)[(c)+1], fmaf(gwk(2), (X)[(c)+2],\
    fmaf(gwk(3), (X)[(c)+3], fmaf(gwk(4), (X)[(c)+4], fmaf(gwk(5), (X)[(c)+5],\
    fmaf(gwk(6), (X)[(c)+6], fmaf(gwk(7), (X)[(c)+7], fmaf(gwk(8), (X)[(c)+8],\
    fmaf(gwk(9), (X)[(c)+9], gwk(10) * (X)[(c)+10]))))))))))

static __device__ double   g_acc = 0.0;
static __device__ unsigned g_cnt = 0u;

__global__ __launch_bounds__(NTHREADS, 3)
void ssim_kernel(const float* __restrict__ img1, const float* __restrict__ img2,
                 float* __restrict__ out) {
    extern __shared__ float sm[];    // [0: a][PLANE: b][HOFF: H planes]
    __shared__ float red[NWARPS];

    const int t    = threadIdx.x;
    const int lane = t & 31;
    const int wid  = t >> 5;        // 0..11
    const int gx0  = blockIdx.x * TW - HALO;
    const int gy0  = blockIdx.y * TH - HALO;
    const float* base1 = img1 + (size_t)blockIdx.z * (IMG * IMG);
    const float* base2 = img2 + (size_t)blockIdx.z * (IMG * IMG);

    // ---- Phase 1: stage a,b (zero-padded), warp per row, coalesced ----
    for (int r = wid; r < ROWS; r += NWARPS) {
        const int gy = gy0 + r;
        const bool yok = (unsigned)gy < (unsigned)IMG;
        const float* r1 = base1 + gy * IMG;
        const float* r2 = base2 + gy * IMG;
        const int o = r * SROW;
#pragma unroll
        for (int seg = 0; seg < 2; seg++) {
            const int c = lane + seg * 32;
            if (seg == 1 && lane >= 10) break;
            const int gx = gx0 + c;
            const bool ok = yok && (unsigned)gx < (unsigned)IMG;
            sm[o + c]         = ok ? r1[gx] : 0.0f;
            sm[PLANE + o + c] = ok ? r2[gx] : 0.0f;
        }
    }
    __syncthreads();

    // ---- Phase 2: horizontal conv of 5 channels from a,b windows ----
    // 296 tasks (quarter-rows, 8 outputs each); quarter-major keeps lanes on
    // consecutive rows -> STS banks (r mod 32) conflict-free.
    if (t < 4 * ROWS) {
        const int q = t / ROWS;          // quarter 0..3
        const int r = t - q * ROWS;      // row 0..73
        const int cbase = q * 8;

        float xa[20], xb[20];
#pragma unroll
        for (int i = 0; i < 5; i++) {
            const float4 va = *reinterpret_cast<const float4*>(&sm[r * SROW + cbase + 4 * i]);
            xa[4*i+0] = va.x; xa[4*i+1] = va.y; xa[4*i+2] = va.z; xa[4*i+3] = va.w;
            const float4 vb = *reinterpret_cast<const float4*>(&sm[PLANE + r * SROW + cbase + 4 * i]);
            xb[4*i+0] = vb.x; xb[4*i+1] = vb.y; xb[4*i+2] = vb.z; xb[4*i+3] = vb.w;
        }

        float* hb = &sm[HOFF + cbase * HCOL + r];
#pragma unroll
        for (int j = 0; j < 8; j++) {
            float mA = 0.f, mB = 0.f, s1 = 0.f, s2 = 0.f, pp = 0.f;
#pragma unroll
            for (int k = 0; k < 11; k++) {
                const float a = xa[j + k];
                const float b = xb[j + k];
                const float wa = gwk(k) * a;
                const float wb = gwk(k) * b;
                mA += wa;
                mB += wb;
                s1 = fmaf(wa, a, s1);
                s2 = fmaf(wb, b, s2);
                pp = fmaf(wa, b, pp);
            }
            float* h = hb + j * HCOL;
            h[0 * HP] = mA;
            h[1 * HP] = mB;
            h[2 * HP] = s1;
            h[3 * HP] = s2;
            h[4 * HP] = pp;
        }
    }
    __syncthreads();

    // ---- Phase 3: vertical conv (aligned float4 column reads) + SSIM ----
    {
        // warps 0..7: 6 rows from r0=6w ; warps 8..11: 4 rows from 48+4(w-8)
        const int six = (wid < 8);
        const int r0  = six ? 6 * wid : 48 + 4 * (wid - 8);
        const int cnt = six ? 6 : 4;
        const int rb  = r0 & ~3;        // 16B-aligned load base
        const int col = lane;

        float res[5][6];
#pragma unroll
        for (int ch = 0; ch < 5; ch++) {
            const float* p = &sm[HOFF + ch * HP + col * HCOL + rb];
            float y[20];
#pragma unroll
            for (int i = 0; i < 5; i++) {
                const float4 v = *reinterpret_cast<const float4*>(p + 4 * i);
                y[4*i+0] = v.x; y[4*i+1] = v.y; y[4*i+2] = v.z; y[4*i+3] = v.w;
            }
            if (r0 & 2) {               // warp-uniform residue path (d = 2)
#pragma unroll
                for (int i = 0; i < 6; i++) res[ch][i] = CONV11(y, i + 2);
            } else {                    // d = 0
#pragma unroll
                for (int i = 0; i < 6; i++) res[ch][i] = CONV11(y, i);
            }
        }

        float lsum = 0.0f;
#pragma unroll
        for (int i = 0; i < 6; i++) {
            const float m1  = res[0][i];
            const float m2  = res[1][i];
            const float m1s = m1 * m1;
            const float m2s = m2 * m2;
            const float m12 = m1 * m2;
            const float s1  = res[2][i] - m1s;
            const float s2  = res[3][i] - m2s;
            const float s12 = res[4][i] - m12;
            const float num = (2.0f * m12 + SSIM_C1) * (2.0f * s12 + SSIM_C2);
            const float den = (m1s + m2s + SSIM_C1) * (s1 + s2 + SSIM_C2);
            const float v   = __fdividef(num, den);
            lsum += (i < cnt) ? v : 0.0f;     // select, never mul (NaN-safe)
        }

        // warp reduce -> block reduce -> one global atomic per block
#pragma unroll
        for (int off = 16; off > 0; off >>= 1)
            lsum += __shfl_xor_sync(0xffffffffu, lsum, off);
        if (lane == 0) red[wid] = lsum;
        __syncthreads();
        if (t == 0) {
            float s = 0.0f;
#pragma unroll
            for (int i = 0; i < NWARPS; i++) s += red[i];
            atomicAdd(&g_acc, (double)s);
            __threadfence();
            const unsigned old = atomicAdd(&g_cnt, 1u);
            if (old == NBLOCKS - 1) {
                const ull raw = atomicExch(reinterpret_cast<ull*>(&g_acc), 0ull);
                out[0] = (float)(__longlong_as_double(raw) * (1.0 / 16777216.0));
                g_cnt = 0u;
            }
        }
    }
}

extern "C" void kernel_launch(void* const* d_in, const int* in_sizes, int n_in,
                              void* d_out, int out_size) {
    const float* img1 = (const float*)d_in[0];
    const float* img2 = (const float*)d_in[1];
    float* out = (float*)d_out;

    cudaFuncSetAttribute(ssim_kernel,
                         cudaFuncAttributeMaxDynamicSharedMemorySize, SMEM_BYTES);

    dim3 grid(IMG / TW, IMG / TH, 64);   // 16 x 8 x 64 = 8192 blocks
    ssim_kernel<<<grid, NTHREADS, SMEM_BYTES>>>(img1, img2, out);
}

// round 9
// speedup vs baseline: 1.7234x; 1.1656x over previous
#include <cuda_runtime.h>

// ---------------------------------------------------------------------------
// SSIM fused single-kernel. Tile 32x64 outputs/block, 384 threads, 3 CTAs/SM.
//   P1: stage interleaved AB plane (float2, zero-padded)        [27.2 KB]
//   P2: horizontal 11-tap conv, packed f32x2 scatter form:
//       (mu1,mu2) and (E11,E22) as packed accumulators, E12 scalar;
//       unpacked stores -> 5 transposed scalar H planes          [48.6 KB]
//   P3: vertical 11-tap conv via aligned float4 column reads + SSIM + reduce
// ---------------------------------------------------------------------------

typedef unsigned long long ull;

#define IMG      512
#define TW       32
#define TH       64
#define HALO     5
#define ROWS     74                // TH + 2*HALO
#define ABROW    46                // AB plane row stride in float2 units
#define ABPLANE  (ROWS * ABROW)    // 3404 float2 = 6808 floats
#define NTHREADS 384
#define NWARPS   12
#define NBLOCKS  (16 * 8 * 64)     // 8192

#define HCOL     76                // H column stride (mult of 4)
#define HP       (32 * HCOL)       // 2432 floats per H plane
#define HOFF     (2 * ABPLANE)     // H starts after AB plane (in floats)

// +16 float pad: P3 warp 11 float4 over-read stays in-bounds (values unused)
#define SMEM_BYTES ((HOFF + 5 * HP + 16) * (int)sizeof(float))   // 75,936 B

#define SSIM_C1 0.0001f
#define SSIM_C2 0.0009f

// 1-D Gaussian, sigma=1.5, 11 taps, normalized (literals -> FFMA-imm)
static __device__ __forceinline__ float gwk(int k) {
    const float g[11] = { 1.0283735e-03f, 7.5987582e-03f, 3.6000773e-02f,
                          1.0936068e-01f, 2.1300554e-01f, 2.6601174e-01f,
                          2.1300554e-01f, 1.0936068e-01f, 3.6000773e-02f,
                          7.5987582e-03f, 1.0283735e-03f };
    return g[k];   // k compile-time under full unroll -> immediate
}

#define CONV11(X, c)                                                          \
    fmaf(gwk(0), (X)[(c)+0], fmaf(gwk(1), (X)[(c)+1], fmaf(gwk(2), (X)[(c)+2],\
    fmaf(gwk(3), (X)[(c)+3], fmaf(gwk(4), (X)[(c)+4], fmaf(gwk(5), (X)[(c)+5],\
    fmaf(gwk(6), (X)[(c)+6], fmaf(gwk(7), (X)[(c)+7], fmaf(gwk(8), (X)[(c)+8],\
    fmaf(gwk(9), (X)[(c)+9], gwk(10) * (X)[(c)+10]))))))))))

// packed f32x2 helpers
__device__ __forceinline__ ull pk2(float lo, float hi) {
    ull d; asm("mov.b64 %0, {%1, %2};" : "=l"(d) : "f"(lo), "f"(hi)); return d;
}
__device__ __forceinline__ void unpk2(ull v, float& lo, float& hi) {
    asm("mov.b64 {%0, %1}, %2;" : "=f"(lo), "=f"(hi) : "l"(v));
}
__device__ __forceinline__ ull mul2(ull a, ull b) {
    ull d; asm("mul.rn.f32x2 %0, %1, %2;" : "=l"(d) : "l"(a), "l"(b)); return d;
}
__device__ __forceinline__ ull fma2(ull a, ull b, ull c) {
    ull d; asm("fma.rn.f32x2 %0, %1, %2, %3;" : "=l"(d) : "l"(a), "l"(b), "l"(c)); return d;
}

static __device__ double   g_acc = 0.0;
static __device__ unsigned g_cnt = 0u;

__global__ __launch_bounds__(NTHREADS, 3)
void ssim_kernel(const float* __restrict__ img1, const float* __restrict__ img2,
                 float* __restrict__ out) {
    extern __shared__ float sm[];    // [AB float2 plane][5 scalar H planes]
    float2* sAB = reinterpret_cast<float2*>(sm);
    __shared__ float red[NWARPS];

    const int t    = threadIdx.x;
    const int lane = t & 31;
    const int wid  = t >> 5;        // 0..11
    const int gx0  = blockIdx.x * TW - HALO;
    const int gy0  = blockIdx.y * TH - HALO;
    const float* base1 = img1 + (size_t)blockIdx.z * (IMG * IMG);
    const float* base2 = img2 + (size_t)blockIdx.z * (IMG * IMG);

    // ---- Phase 1: stage interleaved AB (zero-padded), warp per row ----
    for (int r = wid; r < ROWS; r += NWARPS) {
        const int gy = gy0 + r;
        const bool yok = (unsigned)gy < (unsigned)IMG;
        const float* r1 = base1 + gy * IMG;
        const float* r2 = base2 + gy * IMG;
#pragma unroll
        for (int seg = 0; seg < 2; seg++) {
            const int c = lane + seg * 32;
            if (seg == 1 && lane >= 10) break;
            const int gx = gx0 + c;
            const bool ok = yok && (unsigned)gx < (unsigned)IMG;
            sAB[r * ABROW + c] = make_float2(ok ? r1[gx] : 0.0f,
                                             ok ? r2[gx] : 0.0f);
        }
    }
    __syncthreads();

    // ---- Phase 2: horizontal conv, packed scatter, 2 halves of 4 outputs ----
    // 296 tasks (quarter q = 8 cols, row r); lanes map to consecutive rows.
    if (t < 4 * ROWS) {
        const int q = t / ROWS;          // 0..3
        const int r = t - q * ROWS;      // 0..73
        const int cbase = q * 8;
        const float2* abrow = sAB + r * ABROW;

        ull W2[6];
#pragma unroll
        for (int k = 0; k < 6; k++) W2[k] = pk2(gwk(k), gwk(k));

#pragma unroll
        for (int half = 0; half < 2; half++) {
            const int base = cbase + half * 4;   // first output col of half
            ull  mAB[4] = {0ull, 0ull, 0ull, 0ull};
            ull  sSQ[4] = {0ull, 0ull, 0ull, 0ull};
            float pp[4] = {0.f, 0.f, 0.f, 0.f};

            // stream 14 window elements as 7x LDS.128 (2 packed pairs each)
#pragma unroll
            for (int blk = 0; blk < 7; blk++) {
                const ulonglong2 v = *reinterpret_cast<const ulonglong2*>(
                    abrow + base + 2 * blk);
#pragma unroll
                for (int sub = 0; sub < 2; sub++) {
                    const int e = 2 * blk + sub;      // 0..13, compile-time
                    const ull ab = sub ? v.y : v.x;
                    float a, b;
                    unpk2(ab, a, b);
                    const ull   sq   = mul2(ab, ab);
                    const float prod = a * b;
#pragma unroll
                    for (int j = 0; j < 4; j++) {
                        const int k = e - j;          // compile-time
                        if (k >= 0 && k < 11) {
                            const int ks = (k < 6) ? k : 10 - k;
                            mAB[j] = fma2(W2[ks], ab, mAB[j]);
                            sSQ[j] = fma2(W2[ks], sq, sSQ[j]);
                            pp[j]  = fmaf(gwk(k), prod, pp[j]);
                        }
                    }
                }
            }

            // unpack + store into 5 scalar H planes (banks r mod 32: clean)
#pragma unroll
            for (int j = 0; j < 4; j++) {
                float m1, m2, e11, e22;
                unpk2(mAB[j], m1, m2);
                unpk2(sSQ[j], e11, e22);
                float* h = &sm[HOFF + (base + j) * HCOL + r];
                h[0 * HP] = m1;
                h[1 * HP] = m2;
                h[2 * HP] = e11;
                h[3 * HP] = e22;
                h[4 * HP] = pp[j];
            }
        }
    }
    __syncthreads();

    // ---- Phase 3: vertical conv (aligned float4 column reads) + SSIM ----
    {
        // warps 0..7: 6 rows from r0=6w ; warps 8..11: 4 rows from 48+4(w-8)
        const int six = (wid < 8);
        const int r0  = six ? 6 * wid : 48 + 4 * (wid - 8);
        const int cnt = six ? 6 : 4;
        const int rb  = r0 & ~3;        // 16B-aligned load base
        const int col = lane;

        float res[5][6];
#pragma unroll
        for (int ch = 0; ch < 5; ch++) {
            const float* p = &sm[HOFF + ch * HP + col * HCOL + rb];
            float y[20];
#pragma unroll
            for (int i = 0; i < 5; i++) {
                const float4 v = *reinterpret_cast<const float4*>(p + 4 * i);
                y[4*i+0] = v.x; y[4*i+1] = v.y; y[4*i+2] = v.z; y[4*i+3] = v.w;
            }
            if (r0 & 2) {               // warp-uniform residue path
#pragma unroll
                for (int i = 0; i < 6; i++) res[ch][i] = CONV11(y, i + 2);
            } else {
#pragma unroll
                for (int i = 0; i < 6; i++) res[ch][i] = CONV11(y, i);
            }
        }

        float lsum = 0.0f;
#pragma unroll
        for (int i = 0; i < 6; i++) {
            const float m1  = res[0][i];
            const float m2  = res[1][i];
            const float m1s = m1 * m1;
            const float m2s = m2 * m2;
            const float m12 = m1 * m2;
            const float s1  = res[2][i] - m1s;
            const float s2  = res[3][i] - m2s;
            const float s12 = res[4][i] - m12;
            const float num = (2.0f * m12 + SSIM_C1) * (2.0f * s12 + SSIM_C2);
            const float den = (m1s + m2s + SSIM_C1) * (s1 + s2 + SSIM_C2);
            const float v   = __fdividef(num, den);
            lsum += (i < cnt) ? v : 0.0f;     // select, never mul (NaN-safe)
        }

        // warp reduce -> block reduce -> one global atomic per block
#pragma unroll
        for (int off = 16; off > 0; off >>= 1)
            lsum += __shfl_xor_sync(0xffffffffu, lsum, off);
        if (lane == 0) red[wid] = lsum;
        __syncthreads();
        if (t == 0) {
            float s = 0.0f;
#pragma unroll
            for (int i = 0; i < NWARPS; i++) s += red[i];
            atomicAdd(&g_acc, (double)s);
            __threadfence();
            const unsigned old = atomicAdd(&g_cnt, 1u);
            if (old == NBLOCKS - 1) {
                const ull raw = atomicExch(reinterpret_cast<ull*>(&g_acc), 0ull);
                out[0] = (float)(__longlong_as_double(raw) * (1.0 / 16777216.0));
                g_cnt = 0u;
            }
        }
    }
}

extern "C" void kernel_launch(void* const* d_in, const int* in_sizes, int n_in,
                              void* d_out, int out_size) {
    const float* img1 = (const float*)d_in[0];
    const float* img2 = (const float*)d_in[1];
    float* out = (float*)d_out;

    cudaFuncSetAttribute(ssim_kernel,
                         cudaFuncAttributeMaxDynamicSharedMemorySize, SMEM_BYTES);

    dim3 grid(IMG / TW, IMG / TH, 64);   // 16 x 8 x 64 = 8192 blocks
    ssim_kernel<<<grid, NTHREADS, SMEM_BYTES>>>(img1, img2, out);
}